// round 4
// baseline (speedup 1.0000x reference)
#include <cuda_runtime.h>
#include <cstddef>

// YOLOv3 head decode, B=16, 3 levels (19/38/76), 80 classes, 3 anchors.
// Output layout: d_out = [boxes B*22743*4][scores B*22743*80] (tuple flatten).
// Resubmission of Round-2 source: prior failures were broker-side
// ("GB300 container failed twice"), seen identically on the empty stub.

#define AN_NUM 3
#define NCLS 80
#define NFIELDS 85          // 5 + NCLS
#define CCH (AN_NUM + AN_NUM * NFIELDS)   // 258
#define BATCH 16
#define NTOT 22743
#define EPSV 1e-7f

__device__ __forceinline__ float sigmoidf_fast(float x) {
    // relative accuracy ~1e-6 across the range (exp-based, not tanh.approx)
    return __fdividef(1.0f, 1.0f + __expf(-x));
}

template<int H, int W, int STRIDE>
__global__ __launch_bounds__(256)
void yolo_decode_kernel(const float* __restrict__ in,      // [B, 258, H, W]
                        const float* __restrict__ im_size, // [B, 2] (h, w)
                        float* __restrict__ boxes,         // [B, NTOT, 4]
                        float* __restrict__ scores,        // [B, NTOT, 80]
                        int row_offset,
                        float aw0, float ah0, float aw1, float ah1,
                        float aw2, float ah2)
{
    constexpr int HW   = H * W;
    constexpr int ROWS = HW * AN_NUM;

    int t = blockIdx.x * blockDim.x + threadIdx.x;
    if (t >= BATCH * ROWS) return;

    int b     = t / ROWS;
    int local = t - b * ROWS;
    int pos   = local / AN_NUM;
    int a     = local - pos * AN_NUM;
    int hh    = pos / W;
    int ww    = pos - hh * W;

    const float* inb = in + (size_t)b * CCH * HW;

    // iou prediction channel a
    float ip = sigmoidf_fast(inb[(size_t)a * HW + pos]);

    int ch0 = AN_NUM + a * NFIELDS;
    const float* f = inb + (size_t)ch0 * HW + pos;

    float dx   = f[0];
    float dy   = f[(size_t)1 * HW];
    float dw   = f[(size_t)2 * HW];
    float dh   = f[(size_t)3 * HW];
    float tobj = f[(size_t)4 * HW];

    float obj = sigmoidf_fast(tobj);

    // new_obj = obj^0.6 * ip^0.4  (obj, ip in (0,1): log2 safe)
    float new_obj = exp2f(0.6f * __log2f(obj) + 0.4f * __log2f(ip));

    // conf = sigmoid(de_sigmoid(new_obj)) with reference clipping semantics
    float tt = fminf(fmaxf(new_obj, EPSV), 1e7f);
    float u  = __fdividef(1.0f, tt) - 1.0f;
    u        = fminf(fmaxf(u, EPSV), 1e7f);
    float conf = __fdividef(1.0f, 1.0f + u);

    // box center in input-pixel space
    float x = (1.05f * sigmoidf_fast(dx) + (float)ww - 0.025f) * (float)STRIDE;
    float y = (1.05f * sigmoidf_fast(dy) + (float)hh - 0.025f) * (float)STRIDE;

    float aw = (a == 0) ? aw0 : ((a == 1) ? aw1 : aw2);
    float ah = (a == 0) ? ah0 : ((a == 1) ? ah1 : ah2);
    float bw = __expf(dw) * aw;
    float bh = __expf(dh) * ah;

    float imh = im_size[b * 2 + 0];
    float imw = im_size[b * 2 + 1];
    constexpr float inv = 1.0f / (float)(H * STRIDE);
    float sx = imw * inv;
    float sy = imh * inv;

    float x0 = (x - 0.5f * bw) * sx;
    float y0 = (y - 0.5f * bh) * sy;
    float x1 = (x + 0.5f * bw) * sx;
    float y1 = (y + 0.5f * bh) * sy;
    // reference: lower clamp only on p0, upper clamp only on p1
    x0 = fmaxf(x0, 0.0f);
    y0 = fmaxf(y0, 0.0f);
    x1 = fminf(x1, imw);
    y1 = fminf(y1, imh);

    size_t orow = (size_t)b * NTOT + (size_t)row_offset + (size_t)local;

    *reinterpret_cast<float4*>(boxes + orow * 4) = make_float4(x0, y0, x1, y1);

    float* sptr = scores + orow * (size_t)NCLS;
    const float* p = f + (size_t)5 * HW;
    #pragma unroll
    for (int c = 0; c < NCLS; c += 4) {
        float s0 = conf * sigmoidf_fast(p[(size_t)(c + 0) * HW]);
        float s1 = conf * sigmoidf_fast(p[(size_t)(c + 1) * HW]);
        float s2 = conf * sigmoidf_fast(p[(size_t)(c + 2) * HW]);
        float s3 = conf * sigmoidf_fast(p[(size_t)(c + 3) * HW]);
        *reinterpret_cast<float4*>(sptr + c) = make_float4(s0, s1, s2, s3);
    }
}

extern "C" void kernel_launch(void* const* d_in, const int* in_sizes, int n_in,
                              void* d_out, int out_size)
{
    const float* out0 = (const float*)d_in[0];
    const float* out1 = (const float*)d_in[1];
    const float* out2 = (const float*)d_in[2];
    const float* imsz = (const float*)d_in[3];

    float* boxes  = (float*)d_out;
    float* scores = boxes + (size_t)BATCH * NTOT * 4;

    // level 0: 19x19, stride 32
    {
        int threads = BATCH * 19 * 19 * AN_NUM;
        int blocks = (threads + 255) / 256;
        yolo_decode_kernel<19, 19, 32><<<blocks, 256>>>(
            out0, imsz, boxes, scores, 0,
            116.0f, 90.0f, 156.0f, 198.0f, 373.0f, 326.0f);
    }
    // level 1: 38x38, stride 16
    {
        int threads = BATCH * 38 * 38 * AN_NUM;
        int blocks = (threads + 255) / 256;
        yolo_decode_kernel<38, 38, 16><<<blocks, 256>>>(
            out1, imsz, boxes, scores, 19 * 19 * AN_NUM,
            30.0f, 61.0f, 62.0f, 45.0f, 59.0f, 119.0f);
    }
    // level 2: 76x76, stride 8
    {
        int threads = BATCH * 76 * 76 * AN_NUM;
        int blocks = (threads + 255) / 256;
        yolo_decode_kernel<76, 76, 8><<<blocks, 256>>>(
            out2, imsz, boxes, scores, (19 * 19 + 38 * 38) * AN_NUM,
            10.0f, 13.0f, 16.0f, 30.0f, 33.0f, 23.0f);
    }
}

// round 6
// speedup vs baseline: 1.5576x; 1.5576x over previous
#include <cuda_runtime.h>
#include <cstddef>

// YOLOv3 head decode, fused single kernel over all 3 levels.
// B=16, levels 19/38/76, 80 classes, 3 anchors.
// Output: d_out = [boxes B*22743*4][scores B*22743*80].
// Flat output row r in [0, 363888) maps directly to (b, level, local):
//   b = r / 22743, w = r % 22743; level by threshold {1083, 5415}.
// Scores staged via smem so global stores are 64B-aligned 64B runs
// (4 lanes/row) instead of 16B scattered at 320B stride.
// (Resubmission: previous round hit broker-side container failure.)

#define NCLS 80
#define NTOT 22743
#define BATCH 16
#define TOTAL_ROWS (BATCH * NTOT)   // 363888
#define EPSV 1e-7f

// per-row smem stride for a 16-float chunk (+4 pad words: conflict-free STS.128)
#define SROW 20

__constant__ float c_anch[3][3][2] = {
    {{116.0f, 90.0f}, {156.0f, 198.0f}, {373.0f, 326.0f}},
    {{ 30.0f, 61.0f}, { 62.0f,  45.0f}, { 59.0f, 119.0f}},
    {{ 10.0f, 13.0f}, { 16.0f,  30.0f}, { 33.0f,  23.0f}},
};

__device__ __forceinline__ float sigmoidf_fast(float x) {
    return __fdividef(1.0f, 1.0f + __expf(-x));
}

__global__ __launch_bounds__(256)
void yolo_fused_kernel(const float* __restrict__ in0,
                       const float* __restrict__ in1,
                       const float* __restrict__ in2,
                       const float* __restrict__ im_size,
                       float* __restrict__ boxes,
                       float* __restrict__ scores)
{
    __shared__ float s[256 * SROW];   // 20 KB

    const int tid      = threadIdx.x;
    const int base_row = blockIdx.x * 256;
    const int r_glob   = base_row + tid;
    const bool valid   = (r_glob < TOTAL_ROWS);

    float conf = 0.0f;
    const float* p = in0;   // class-prob channel 0 base for this row
    int HW = 1;

    if (valid) {
        int b = r_glob / NTOT;
        int w = r_glob - b * NTOT;

        int level, off, Wd, stride;
        const float* in;
        if (w < 1083)       { level = 0; off = 0;    in = in0; HW = 361;  Wd = 19; stride = 32; }
        else if (w < 5415)  { level = 1; off = 1083; in = in1; HW = 1444; Wd = 38; stride = 16; }
        else                { level = 2; off = 5415; in = in2; HW = 5776; Wd = 76; stride = 8;  }

        int local = w - off;
        int pos = local / 3;
        int a   = local - pos * 3;
        int hh  = pos / Wd;
        int ww  = pos - hh * Wd;

        const float* inb = in + (size_t)b * 258 * HW;

        // iou-aware objectness
        float ip = sigmoidf_fast(inb[(size_t)a * HW + pos]);

        const float* f = inb + (size_t)(3 + a * 85) * HW + pos;
        float dx   = f[0];
        float dy   = f[(size_t)1 * HW];
        float dw   = f[(size_t)2 * HW];
        float dh   = f[(size_t)3 * HW];
        float tobj = f[(size_t)4 * HW];

        float obj = sigmoidf_fast(tobj);
        // new_obj = obj^0.6 * ip^0.4 (both in (0,1))
        float new_obj = exp2f(0.6f * __log2f(obj) + 0.4f * __log2f(ip));

        // conf = sigmoid(de_sigmoid(new_obj)), reference clipping semantics
        float tt = fminf(fmaxf(new_obj, EPSV), 1e7f);
        float u  = __fdividef(1.0f, tt) - 1.0f;
        u        = fminf(fmaxf(u, EPSV), 1e7f);
        conf     = __fdividef(1.0f, 1.0f + u);

        // box
        float x = (1.05f * sigmoidf_fast(dx) + (float)ww - 0.025f) * (float)stride;
        float y = (1.05f * sigmoidf_fast(dy) + (float)hh - 0.025f) * (float)stride;
        float aw = c_anch[level][a][0];
        float ah = c_anch[level][a][1];
        float bw = __expf(dw) * aw;
        float bh = __expf(dh) * ah;

        float imh = im_size[b * 2 + 0];
        float imw = im_size[b * 2 + 1];
        float inv = __fdividef(1.0f, (float)(HW == 361 ? 19 * 32 : (HW == 1444 ? 38 * 16 : 76 * 8)));
        float sx = imw * inv;
        float sy = imh * inv;

        float x0 = fmaxf((x - 0.5f * bw) * sx, 0.0f);
        float y0 = fmaxf((y - 0.5f * bh) * sy, 0.0f);
        float x1 = fminf((x + 0.5f * bw) * sx, imw);
        float y1 = fminf((y + 0.5f * bh) * sy, imh);

        *reinterpret_cast<float4*>(boxes + (size_t)r_glob * 4) =
            make_float4(x0, y0, x1, y1);

        p = f + (size_t)5 * HW;
    }

    // scores: 5 chunks of 16 classes, staged through smem for coalesced stores
    #pragma unroll
    for (int c0 = 0; c0 < NCLS; c0 += 16) {
        if (valid) {
            #pragma unroll
            for (int g = 0; g < 4; ++g) {
                int c = c0 + g * 4;
                float4 v;
                v.x = conf * sigmoidf_fast(p[(size_t)(c + 0) * HW]);
                v.y = conf * sigmoidf_fast(p[(size_t)(c + 1) * HW]);
                v.z = conf * sigmoidf_fast(p[(size_t)(c + 2) * HW]);
                v.w = conf * sigmoidf_fast(p[(size_t)(c + 3) * HW]);
                *reinterpret_cast<float4*>(&s[tid * SROW + g * 4]) = v;
            }
        }
        __syncthreads();

        // write 256 rows x 16 floats: 4 lanes per row, 64B-aligned 64B runs
        #pragma unroll
        for (int k = 0; k < 4; ++k) {
            int idx = tid + k * 256;
            int rr  = idx >> 2;
            int q   = idx & 3;
            int row = base_row + rr;
            if (row < TOTAL_ROWS) {
                float4 v = *reinterpret_cast<const float4*>(&s[rr * SROW + q * 4]);
                *reinterpret_cast<float4*>(&scores[(size_t)row * NCLS + c0 + q * 4]) = v;
            }
        }
        __syncthreads();
    }
}

extern "C" void kernel_launch(void* const* d_in, const int* in_sizes, int n_in,
                              void* d_out, int out_size)
{
    const float* out0 = (const float*)d_in[0];
    const float* out1 = (const float*)d_in[1];
    const float* out2 = (const float*)d_in[2];
    const float* imsz = (const float*)d_in[3];

    float* boxes  = (float*)d_out;
    float* scores = boxes + (size_t)BATCH * NTOT * 4;

    int blocks = (TOTAL_ROWS + 255) / 256;   // 1422
    yolo_fused_kernel<<<blocks, 256>>>(out0, out1, out2, imsz, boxes, scores);
}

// round 7
// speedup vs baseline: 1.6267x; 1.0444x over previous
#include <cuda_runtime.h>
#include <cstddef>

// YOLOv3 head decode, fused, anchor-grouped compute mapping.
// Block = 384 threads = 128 consecutive positions x 3 anchors of one (b, level).
// Warps are anchor-pure -> channel-plane loads are perfectly coalesced.
// Output rows of a block form a contiguous span; boxes and scores staged
// through smem for coalesced stores.
// Output: d_out = [boxes 16*22743*4][scores 16*22743*80].

#define NCLS 80
#define NTOT 22743
#define BATCH 16
#define EPSV 1e-7f
#define SROW 20              // smem row stride for a 16-float chunk (+4 pad)
#define BLK 384
#define POSB 128             // positions per block
#define LBLK 61              // blocks per batch: 3 + 12 + 46

__constant__ float c_anch[3][3][2] = {
    {{116.0f, 90.0f}, {156.0f, 198.0f}, {373.0f, 326.0f}},
    {{ 30.0f, 61.0f}, { 62.0f,  45.0f}, { 59.0f, 119.0f}},
    {{ 10.0f, 13.0f}, { 16.0f,  30.0f}, { 33.0f,  23.0f}},
};

__device__ __forceinline__ float sigmoidf_fast(float x) {
    return __fdividef(1.0f, 1.0f + __expf(-x));
}

__global__ __launch_bounds__(BLK)
void yolo_fused_kernel(const float* __restrict__ in0,
                       const float* __restrict__ in1,
                       const float* __restrict__ in2,
                       const float* __restrict__ im_size,
                       float* __restrict__ boxes,
                       float* __restrict__ scores)
{
    __shared__ float s[BLK * SROW];   // 30 KB; box phase reuses the front

    const int tid  = threadIdx.x;
    const int b    = blockIdx.x / LBLK;
    const int lid  = blockIdx.x - b * LBLK;

    int level, pos0, HW, Wd, stride, off;
    const float* in;
    if (lid < 3)        { level = 0; pos0 = lid * POSB;        HW = 361;  Wd = 19; stride = 32; off = 0;    in = in0; }
    else if (lid < 15)  { level = 1; pos0 = (lid - 3) * POSB;  HW = 1444; Wd = 38; stride = 16; off = 1083; in = in1; }
    else                { level = 2; pos0 = (lid - 15) * POSB; HW = 5776; Wd = 76; stride = 8;  off = 5415; in = in2; }

    const int a   = tid / POSB;            // warp-pure anchor id
    const int i   = tid - a * POSB;
    const int pos = pos0 + i;
    const bool valid = (pos < HW);
    const int valid_rows = min(BLK, (HW - pos0) * 3);
    const int row_local  = i * 3 + a;
    const size_t row0 = (size_t)b * NTOT + off + (size_t)pos0 * 3;

    float conf = 0.0f;
    const float* p = in0;   // class-prob base for this thread's row

    if (valid) {
        const float* inb = in + (size_t)b * 258 * HW;

        float ip = sigmoidf_fast(inb[(size_t)a * HW + pos]);

        const float* f = inb + (size_t)(3 + a * 85) * HW + pos;
        float dx   = f[0];
        float dy   = f[(size_t)1 * HW];
        float dw   = f[(size_t)2 * HW];
        float dh   = f[(size_t)3 * HW];
        float tobj = f[(size_t)4 * HW];

        float obj = sigmoidf_fast(tobj);
        // new_obj = obj^0.6 * ip^0.4 (both in (0,1))
        float new_obj = exp2f(0.6f * __log2f(obj) + 0.4f * __log2f(ip));

        // conf = sigmoid(de_sigmoid(new_obj)), reference clipping semantics
        float tt = fminf(fmaxf(new_obj, EPSV), 1e7f);
        float u  = __fdividef(1.0f, tt) - 1.0f;
        u        = fminf(fmaxf(u, EPSV), 1e7f);
        conf     = __fdividef(1.0f, 1.0f + u);

        int hh = pos / Wd;
        int ww = pos - hh * Wd;
        float x = (1.05f * sigmoidf_fast(dx) + (float)ww - 0.025f) * (float)stride;
        float y = (1.05f * sigmoidf_fast(dy) + (float)hh - 0.025f) * (float)stride;
        float bw = __expf(dw) * c_anch[level][a][0];
        float bh = __expf(dh) * c_anch[level][a][1];

        float imh = im_size[b * 2 + 0];
        float imw = im_size[b * 2 + 1];
        const float inv = 1.0f / 608.0f;   // H*stride = 608 for all levels
        float sx = imw * inv;
        float sy = imh * inv;

        float x0 = fmaxf((x - 0.5f * bw) * sx, 0.0f);
        float y0 = fmaxf((y - 0.5f * bh) * sy, 0.0f);
        float x1 = fminf((x + 0.5f * bw) * sx, imw);
        float y1 = fminf((y + 0.5f * bh) * sy, imh);

        *reinterpret_cast<float4*>(&s[row_local * 4]) = make_float4(x0, y0, x1, y1);

        p = f + (size_t)5 * HW;
    }
    __syncthreads();

    // coalesced box store: 384 contiguous rows
    if (tid < valid_rows) {
        float4 v = *reinterpret_cast<const float4*>(&s[tid * 4]);
        *reinterpret_cast<float4*>(&boxes[(row0 + tid) * 4]) = v;
    }
    __syncthreads();

    // scores: 5 chunks of 16 classes, staged through smem
    #pragma unroll
    for (int c0 = 0; c0 < NCLS; c0 += 16) {
        if (valid) {
            #pragma unroll
            for (int g = 0; g < 4; ++g) {
                int c = c0 + g * 4;
                float4 v;
                v.x = conf * sigmoidf_fast(p[(size_t)(c + 0) * HW]);
                v.y = conf * sigmoidf_fast(p[(size_t)(c + 1) * HW]);
                v.z = conf * sigmoidf_fast(p[(size_t)(c + 2) * HW]);
                v.w = conf * sigmoidf_fast(p[(size_t)(c + 3) * HW]);
                *reinterpret_cast<float4*>(&s[row_local * SROW + g * 4]) = v;
            }
        }
        __syncthreads();

        // write BLK rows x 16 floats: 4 lanes/row, 64B runs
        #pragma unroll
        for (int k = 0; k < 4; ++k) {
            int idx = tid + k * BLK;
            int rr  = idx >> 2;
            int q   = idx & 3;
            if (rr < valid_rows) {
                float4 v = *reinterpret_cast<const float4*>(&s[rr * SROW + q * 4]);
                *reinterpret_cast<float4*>(&scores[(row0 + rr) * NCLS + c0 + q * 4]) = v;
            }
        }
        __syncthreads();
    }
}

extern "C" void kernel_launch(void* const* d_in, const int* in_sizes, int n_in,
                              void* d_out, int out_size)
{
    const float* out0 = (const float*)d_in[0];
    const float* out1 = (const float*)d_in[1];
    const float* out2 = (const float*)d_in[2];
    const float* imsz = (const float*)d_in[3];

    float* boxes  = (float*)d_out;
    float* scores = boxes + (size_t)BATCH * NTOT * 4;

    yolo_fused_kernel<<<BATCH * LBLK, BLK>>>(out0, out1, out2, imsz, boxes, scores);
}